// round 9
// baseline (speedup 1.0000x reference)
#include <cuda_runtime.h>
#include <cuda_bf16.h>
#include <cstdint>
#include <math.h>

#define H 2048
#define NBOP 8
#define MAXA 10
#define NENC 9            // NB + 1 encoder rows
#define NPRE (NENC + MAXA) // 19 precomputed w_ih@x vectors: 0..8 enc rows, 9..18 anchors

// ---------------- device state ----------------
__device__ __align__(16) float g_h[2][H];
__device__ __align__(16) float g_c[H];
__device__ __align__(16) float g_aw1[MAXA][H];
__device__ __align__(16) float g_r[H];
__device__ __align__(16) float g_bias[4 * H];                 // b_ih + b_hh
__device__ __align__(16) float g_wih_pre[NPRE][4 * H];        // w_ih @ x for all possible x
__device__ __align__(16) __nv_bfloat16 g_wih_bf[4 * H * H];   // 33.5 MB
__device__ __align__(16) __nv_bfloat16 g_whh_bf[4 * H * H];   // 33.5 MB
__device__ __align__(16) __nv_bfloat16 g_w1_bf[H * H];        // 8.4 MB
__device__ __align__(16) __nv_bfloat16 g_w2_bf[H * H];        // 8.4 MB
__device__ int g_xrow;            // row into g_wih_pre for next cell's input
__device__ unsigned g_ctrA;       // ticket counter: gemv+attn fusion
__device__ unsigned g_ctrB;       // ticket counter: cell+op fusion
__device__ uint32_t g_key[2];
__device__ float g_lp;
__device__ float g_ent;
__device__ float g_arc[64];

// ---------------- threefry2x32 (20 rounds) ----------------
__device__ __forceinline__ uint32_t rotl32(uint32_t v, int d) {
    return (v << d) | (v >> (32 - d));
}

__device__ __forceinline__ void tf2x32(uint32_t k0, uint32_t k1,
                                       uint32_t x0, uint32_t x1,
                                       uint32_t& y0, uint32_t& y1) {
    uint32_t ks0 = k0, ks1 = k1, ks2 = 0x1BD11BDAu ^ k0 ^ k1;
    x0 += ks0; x1 += ks1;
#define TF_RND(r) { x0 += x1; x1 = rotl32(x1, r); x1 ^= x0; }
    TF_RND(13) TF_RND(15) TF_RND(26) TF_RND(6)
    x0 += ks1; x1 += ks2 + 1u;
    TF_RND(17) TF_RND(29) TF_RND(16) TF_RND(24)
    x0 += ks2; x1 += ks0 + 2u;
    TF_RND(13) TF_RND(15) TF_RND(26) TF_RND(6)
    x0 += ks0; x1 += ks1 + 3u;
    TF_RND(17) TF_RND(29) TF_RND(16) TF_RND(24)
    x0 += ks1; x1 += ks2 + 4u;
    TF_RND(13) TF_RND(15) TF_RND(26) TF_RND(6)
    x0 += ks2; x1 += ks0 + 5u;
#undef TF_RND
    y0 = x0; y1 = x1;
}

__device__ __forceinline__ float sigf(float z) { return 1.0f / (1.0f + expf(-z)); }

// JAX partitionable PRNG semantics (VERIFIED rel_err 2.7e-7 in fp32 run — do not touch):
//   split(key):  keys[i] = threefry(key, (0, i))  -> key=keys[0], sub=keys[1]
//   bits(sub,n): bits[i] = y0 ^ y1 of threefry(sub, (0, i))
__device__ int d_sample(const float* L, int n) {
    uint32_t k0 = g_key[0], k1 = g_key[1];
    uint32_t nk0, nk1, sk0, sk1;
    tf2x32(k0, k1, 0u, 0u, nk0, nk1);
    tf2x32(k0, k1, 0u, 1u, sk0, sk1);
    g_key[0] = nk0; g_key[1] = nk1;

    float best = 0.0f; int idx = 0;
    for (int i = 0; i < n; i++) {
        uint32_t b0, b1;
        tf2x32(sk0, sk1, 0u, (uint32_t)i, b0, b1);
        uint32_t bits = b0 ^ b1;
        float f = __uint_as_float((bits >> 9) | 0x3f800000u) - 1.0f;
        float u = (f > 0.0f) ? f : 1.17549435e-38f;
        float z = L[i] - logf(-logf(u));
        if (i == 0 || z > best) { best = z; idx = i; }
    }
    float m = L[0];
    for (int i = 1; i < n; i++) m = fmaxf(m, L[i]);
    float se = 0.0f;
    for (int i = 0; i < n; i++) se += expf(L[i] - m);
    float lse = m + logf(se);
    float ent = 0.0f;
    for (int i = 0; i < n; i++) { float l = L[i] - lse; ent -= l * expf(l); }
    g_lp  += -(L[idx] - lse);
    g_ent += ent;
    return idx;
}

// ---------------- weight conversion (fp32 -> bf16) + bias fuse ----------------
__global__ __launch_bounds__(256) void k_convert(
    const float* __restrict__ w_ih, const float* __restrict__ w_hh,
    const float* __restrict__ w1, const float* __restrict__ w2,
    const float* __restrict__ b_ih, const float* __restrict__ b_hh) {
    const size_t n4 = (size_t)4 * H * H / 4;
    const size_t m4 = (size_t)H * H / 4;
    size_t i = (size_t)blockIdx.x * blockDim.x + threadIdx.x;
    if (i < n4) {
        float4 a = ((const float4*)w_ih)[i];
        float4 b = ((const float4*)w_hh)[i];
        __nv_bfloat162* oi = (__nv_bfloat162*)g_wih_bf;
        __nv_bfloat162* oh = (__nv_bfloat162*)g_whh_bf;
        oi[2 * i]     = __floats2bfloat162_rn(a.x, a.y);
        oi[2 * i + 1] = __floats2bfloat162_rn(a.z, a.w);
        oh[2 * i]     = __floats2bfloat162_rn(b.x, b.y);
        oh[2 * i + 1] = __floats2bfloat162_rn(b.z, b.w);
    }
    if (i < m4) {
        float4 a = ((const float4*)w1)[i];
        float4 b = ((const float4*)w2)[i];
        __nv_bfloat162* o1 = (__nv_bfloat162*)g_w1_bf;
        __nv_bfloat162* o2 = (__nv_bfloat162*)g_w2_bf;
        o1[2 * i]     = __floats2bfloat162_rn(a.x, a.y);
        o1[2 * i + 1] = __floats2bfloat162_rn(a.z, a.w);
        o2[2 * i]     = __floats2bfloat162_rn(b.x, b.y);
        o2[2 * i + 1] = __floats2bfloat162_rn(b.z, b.w);
    }
    if (i < 4 * H) g_bias[i] = b_ih[i] + b_hh[i];
}

// ---------------- precompute w_ih @ enc[k]^T for all 9 encoder rows (fp32) ----------------
__global__ __launch_bounds__(256) void k_precomp(const float* __restrict__ w_ih,
                                                 const float* __restrict__ enc) {
    const int g = blockIdx.x;   // output row 0..4H-1
    const int t = threadIdx.x;
    const float4* __restrict__ wr = (const float4*)(w_ih + (size_t)g * H);
    float4 a0 = wr[t], a1 = wr[t + 256];
    float acc[NENC];
#pragma unroll
    for (int k = 0; k < NENC; k++) {
        const float4* __restrict__ e4 = (const float4*)(enc + (size_t)k * H);
        float4 e0 = e4[t], e1 = e4[t + 256];
        acc[k] = a0.x * e0.x + a0.y * e0.y + a0.z * e0.z + a0.w * e0.w
               + a1.x * e1.x + a1.y * e1.y + a1.z * e1.z + a1.w * e1.w;
    }
    __shared__ float sb[8][NENC];
#pragma unroll
    for (int k = 0; k < NENC; k++) {
        float s = acc[k];
        for (int o = 16; o > 0; o >>= 1) s += __shfl_down_sync(0xffffffffu, s, o);
        if ((t & 31) == 0) sb[t >> 5][k] = s;
    }
    __syncthreads();
    if (t < NENC) {
        float r = 0.f;
        for (int w = 0; w < 8; w++) r += sb[w][t];
        g_wih_pre[t][g] = r;
    }
}

// ---------------- init kernels ----------------
__global__ void k_init() {
    int i = blockIdx.x * blockDim.x + threadIdx.x;
    if (i < H) { g_h[0][i] = 0.0f; g_h[1][i] = 0.0f; g_c[i] = 0.0f; }
    if (i == 0) {
        g_key[0] = 0u; g_key[1] = 42u;
        g_lp = 0.0f; g_ent = 0.0f;
        g_ctrA = 0u; g_ctrB = 0u;
    }
}

// zero anchor-precompute slots 9,10 (warmup anchors are zero vectors); xrow=enc[0]
__global__ void k_sampler_init() {
    int i = blockIdx.x * blockDim.x + threadIdx.x;
    if (i < 4 * H) {
        g_wih_pre[NENC + 0][i] = 0.0f;
        g_wih_pre[NENC + 1][i] = 0.0f;
    }
    if (i == 0) g_xrow = 0;
}

// ---------------- shared helpers ----------------
__device__ __forceinline__ float bdot8(uint4 w, float4 a, float4 b) {
    float2 f0 = __bfloat1622float2(*(__nv_bfloat162*)&w.x);
    float2 f1 = __bfloat1622float2(*(__nv_bfloat162*)&w.y);
    float2 f2 = __bfloat1622float2(*(__nv_bfloat162*)&w.z);
    float2 f3 = __bfloat1622float2(*(__nv_bfloat162*)&w.w);
    return f0.x * a.x + f0.y * a.y + f1.x * a.z + f1.y * a.w
         + f2.x * b.x + f2.y * b.y + f3.x * b.z + f3.y * b.w;
}

// one bf16 row (H elems = 256 uint4) dot h; result valid in t==0
__device__ __forceinline__ float bdot_row(const uint4* __restrict__ wr,
                                          const float4* __restrict__ h4, int t) {
    uint4 w = wr[t];
    float s = bdot8(w, h4[2 * t], h4[2 * t + 1]);
    for (int o = 16; o > 0; o >>= 1) s += __shfl_down_sync(0xffffffffu, s, o);
    __shared__ float sb[8];
    if ((t & 31) == 0) sb[t >> 5] = s;
    __syncthreads();
    float r = 0.f;
    if (t == 0)
        r = sb[0] + sb[1] + sb[2] + sb[3] + sb[4] + sb[5] + sb[6] + sb[7];
    return r;
}

// ---------------- LSTM cell core (whh-only; wih via precomputed table) ----------------
__device__ __forceinline__ void cell_body(int j, int t, int par, int xrow) {
    const float4* __restrict__ h4 = (const float4*)g_h[par];
    float4 ha = h4[2 * t], hb = h4[2 * t + 1];
    const uint4* __restrict__ wh = (const uint4*)g_whh_bf;
    float s0, s1, s2, s3;
    {
        uint4 b;
        b = wh[((size_t)(0 * H + j)) * 256 + t]; s0 = bdot8(b, ha, hb);
        b = wh[((size_t)(1 * H + j)) * 256 + t]; s1 = bdot8(b, ha, hb);
        b = wh[((size_t)(2 * H + j)) * 256 + t]; s2 = bdot8(b, ha, hb);
        b = wh[((size_t)(3 * H + j)) * 256 + t]; s3 = bdot8(b, ha, hb);
    }
    for (int o = 16; o > 0; o >>= 1) {
        s0 += __shfl_down_sync(0xffffffffu, s0, o);
        s1 += __shfl_down_sync(0xffffffffu, s1, o);
        s2 += __shfl_down_sync(0xffffffffu, s2, o);
        s3 += __shfl_down_sync(0xffffffffu, s3, o);
    }
    __shared__ float sb4[8][4];
    if ((t & 31) == 0) {
        sb4[t >> 5][0] = s0; sb4[t >> 5][1] = s1;
        sb4[t >> 5][2] = s2; sb4[t >> 5][3] = s3;
    }
    __syncthreads();
    if (t == 0) {
        float r0 = 0.f, r1 = 0.f, r2 = 0.f, r3 = 0.f;
        for (int w = 0; w < 8; w++) {
            r0 += sb4[w][0]; r1 += sb4[w][1]; r2 += sb4[w][2]; r3 += sb4[w][3];
        }
        r0 += g_wih_pre[xrow][0 * H + j];
        r1 += g_wih_pre[xrow][1 * H + j];
        r2 += g_wih_pre[xrow][2 * H + j];
        r3 += g_wih_pre[xrow][3 * H + j];
        float gi = sigf(r0 + g_bias[0 * H + j]);
        float gf = sigf(r1 + g_bias[1 * H + j]);
        float gg = tanhf(r2 + g_bias[2 * H + j]);
        float go = sigf(r3 + g_bias[3 * H + j]);
        float c2 = gf * g_c[j] + gi * gg;
        g_c[j] = c2;
        g_h[par ^ 1][j] = go * tanhf(c2);
    }
}

// plain cell
__global__ __launch_bounds__(256) void k_cell(int par) {
    cell_body(blockIdx.x, threadIdx.x, par, g_xrow);
}

// ---------------- fused cell + op-sample (last-block tail) ----------------
__global__ __launch_bounds__(256) void k_cellop(const float* __restrict__ w_soft,
                                                const float* __restrict__ b_soft,
                                                const float* __restrict__ b_nl,
                                                int use_bias, int slot, int par) {
    const int t = threadIdx.x;
    cell_body(blockIdx.x, t, par, g_xrow);

    __threadfence();
    __shared__ bool last;
    if (t == 0) last = (atomicAdd(&g_ctrB, 1u) == (unsigned)gridDim.x - 1u);
    __syncthreads();
    if (!last) return;
    if (t == 0) g_ctrB = 0u;

    // tail: logits = h_new @ w_soft^T (+b_soft), squash, sample
    const float* __restrict__ h = g_h[par ^ 1];
    __shared__ float red[256];
    __shared__ float sl[NBOP];
    float part[NBOP];
#pragma unroll
    for (int o = 0; o < NBOP; o++) part[o] = 0.f;
    for (int k = t; k < H; k += 256) {
        float hv = h[k];
#pragma unroll
        for (int o = 0; o < NBOP; o++)
            part[o] += w_soft[(size_t)o * H + k] * hv;
    }
#pragma unroll
    for (int o = 0; o < NBOP; o++) {
        red[t] = part[o];
        __syncthreads();
        for (int s = 128; s > 0; s >>= 1) {
            if (t < s) red[t] += red[t + s];
            __syncthreads();
        }
        if (t == 0) sl[o] = red[0];
        __syncthreads();
    }
    if (t == 0) {
        float L[NBOP];
        for (int o = 0; o < NBOP; o++) {
            L[o] = tanhf((sl[o] + b_soft[o]) / 5.0f);
            if (use_bias) L[o] += b_nl[o];
        }
        int op = d_sample(L, NBOP);
        g_arc[slot] = (float)op;
        g_xrow = op + 1;           // next input = encoder_w[op+1]
    }
}

// ---------------- fused gemv_r + attention-sample (last-block tail) ----------------
__global__ __launch_bounds__(256) void k_gemv_attn(const float* __restrict__ v,
                                                   int n, int slot, int par) {
    const int m = blockIdx.x, t = threadIdx.x;
    const uint4* wr = (const uint4*)(g_w2_bf + (size_t)m * H);
    float s = bdot_row(wr, (const float4*)g_h[par], t);
    if (t == 0) g_r[m] = s;

    __threadfence();
    __shared__ bool last;
    if (t == 0) last = (atomicAdd(&g_ctrA, 1u) == (unsigned)gridDim.x - 1u);
    __syncthreads();
    if (!last) return;
    if (t == 0) g_ctrA = 0u;

    // tail: logits over n anchors, sample, set xrow
    __shared__ float red[256];
    __shared__ float sl[MAXA];
    float part[MAXA];
    for (int l = 0; l < n; l++) part[l] = 0.f;
    for (int k = t; k < H; k += 256) {
        float rv = g_r[k], vv = v[k];
        for (int l = 0; l < n; l++)
            part[l] += vv * tanhf(g_aw1[l][k] + rv);
    }
    for (int l = 0; l < n; l++) {
        red[t] = part[l];
        __syncthreads();
        for (int o = 128; o > 0; o >>= 1) {
            if (t < o) red[t] += red[t + o];
            __syncthreads();
        }
        if (t == 0) sl[l] = red[0];
        __syncthreads();
    }
    if (t == 0) {
        float L[MAXA];
        for (int l = 0; l < n; l++) L[l] = 2.5f * tanhf(sl[l] / 5.0f);
        int idx = d_sample(L, n);
        g_arc[slot] = (float)idx;
        g_xrow = NENC + idx;       // next input = anchors[idx] (precomputed slot)
    }
}

// ---------------- w1 row GEMV; when record: also precompute w_ih@h into anchor slot ----------------
// grid = 2048 (record=0) or 2048+8192 (record=1)
__global__ __launch_bounds__(256) void k_w1row(int a, int par, int record) {
    const int b = blockIdx.x, t = threadIdx.x;
    const float4* __restrict__ h4 = (const float4*)g_h[par];
    if (b < H) {
        const uint4* wr = (const uint4*)(g_w1_bf + (size_t)b * H);
        float s = bdot_row(wr, h4, t);
        if (t == 0) {
            g_aw1[a][b] = s;
            if (record && b == 0) g_xrow = 0;  // inputs reset to encoder_w[0]
        }
    } else {
        const int row = b - H;                 // 0..4H-1
        const uint4* wr = (const uint4*)(g_wih_bf + (size_t)row * H);
        float s = bdot_row(wr, h4, t);
        if (t == 0) g_wih_pre[NENC + a][row] = s;
    }
}

// ---------------- finalize ----------------
__global__ void k_final(float* __restrict__ out, int out_size) {
    int t = threadIdx.x + blockIdx.x * blockDim.x;
    if (t < out_size) out[t] = 0.0f;
    if (t < 64 && t < out_size) out[t] = g_arc[t];
    if (t == 64 && t < out_size) out[t] = g_lp;
    if (t == 65 && t < out_size) out[t] = g_ent;
}

// ---------------- host schedule ----------------
extern "C" void kernel_launch(void* const* d_in, const int* in_sizes, int n_in,
                              void* d_out, int out_size) {
    const float* enc    = (const float*)d_in[0];
    const float* w_ih   = (const float*)d_in[1];
    const float* b_ih   = (const float*)d_in[2];
    const float* w_hh   = (const float*)d_in[3];
    const float* b_hh   = (const float*)d_in[4];
    const float* w_soft = (const float*)d_in[5];
    const float* b_soft = (const float*)d_in[6];
    const float* b_nl   = (const float*)d_in[7];
    const float* w1     = (const float*)d_in[8];
    const float* w2     = (const float*)d_in[9];
    const float* v      = (const float*)d_in[10];

    {
        size_t n4 = (size_t)4 * H * H / 4;
        int blocks = (int)((n4 + 255) / 256);
        k_convert<<<blocks, 256>>>(w_ih, w_hh, w1, w2, b_ih, b_hh);
    }
    k_precomp<<<4 * H, 256>>>(w_ih, enc);

    int par = 0;
    k_init<<<8, 256>>>();
    for (int s = 0; s < 2; s++) {
        int use_bias = (s == 0) ? 1 : 0;
        k_sampler_init<<<32, 256>>>();
        for (int a = 0; a < 2; a++) {
            k_cell<<<H, 256>>>(par); par ^= 1;
            k_w1row<<<H, 256>>>(a, par, 0);
        }
        for (int layer = 2; layer < 10; layer++) {
            int base = s * 32 + 4 * (layer - 2);
            for (int t2 = 0; t2 < 2; t2++) {
                k_cell<<<H, 256>>>(par); par ^= 1;
                k_gemv_attn<<<H, 256>>>(v, layer, base + (t2 ? 2 : 0), par);
            }
            for (int t2 = 0; t2 < 2; t2++) {
                k_cellop<<<H, 256>>>(w_soft, b_soft, b_nl, use_bias,
                                     base + 1 + 2 * t2, par);
                par ^= 1;
            }
            k_cell<<<H, 256>>>(par); par ^= 1;
            k_w1row<<<5 * H, 256>>>(layer, par, 1);
        }
    }
    int nfin = (out_size + 255) / 256;
    if (nfin < 1) nfin = 1;
    k_final<<<nfin, 256>>>((float*)d_out, out_size);
}

// round 14
// speedup vs baseline: 1.0849x; 1.0849x over previous
#include <cuda_runtime.h>
#include <cuda_bf16.h>
#include <cstdint>
#include <math.h>

#define H 2048
#define NBOP 8
#define MAXA 10
#define NENC 9             // NB + 1 encoder rows
#define NPRE (NENC + MAXA) // 19 precomputed w_ih@x rows: 0..8 enc, 9..18 anchors
#define NBLK 148
#define NTHR 1024

// ---------------- device state ----------------
__device__ __align__(16) float g_h[2][H];
__device__ __align__(16) float g_c[H];
__device__ __align__(16) float g_aw1[MAXA][H];
__device__ __align__(16) float g_r[H];
__device__ __align__(16) float g_bias[4 * H];                 // b_ih + b_hh
__device__ __align__(16) float g_wih_pre[NPRE][4 * H];        // w_ih @ x for all possible x
__device__ __align__(16) __nv_bfloat16 g_wih_bf[4 * H * H];   // 33.5 MB
__device__ __align__(16) __nv_bfloat16 g_whh_bf[4 * H * H];   // 33.5 MB
__device__ __align__(16) __nv_bfloat16 g_w1_bf[H * H];        // 8.4 MB
__device__ __align__(16) __nv_bfloat16 g_w2_bf[H * H];        // 8.4 MB
__device__ unsigned g_bar_count;
__device__ volatile unsigned g_bar_gen;

// ---------------- grid barrier (gen reset by k_reset before each replay) ----------------
__device__ __forceinline__ void grid_bar(unsigned& lgen) {
    __syncthreads();
    if (threadIdx.x == 0) {
        unsigned target = ++lgen;
        __threadfence();
        if (atomicAdd(&g_bar_count, 1u) == (unsigned)(NBLK - 1)) {
            g_bar_count = 0u;
            __threadfence();
            g_bar_gen = target;
        } else {
            while (g_bar_gen < target) { __nanosleep(32); }
        }
    }
    __syncthreads();
}

// ---------------- threefry2x32 (20 rounds) ----------------
__device__ __forceinline__ uint32_t rotl32(uint32_t v, int d) {
    return (v << d) | (v >> (32 - d));
}

__device__ __forceinline__ void tf2x32(uint32_t k0, uint32_t k1,
                                       uint32_t x0, uint32_t x1,
                                       uint32_t& y0, uint32_t& y1) {
    uint32_t ks0 = k0, ks1 = k1, ks2 = 0x1BD11BDAu ^ k0 ^ k1;
    x0 += ks0; x1 += ks1;
#define TF_RND(r) { x0 += x1; x1 = rotl32(x1, r); x1 ^= x0; }
    TF_RND(13) TF_RND(15) TF_RND(26) TF_RND(6)
    x0 += ks1; x1 += ks2 + 1u;
    TF_RND(17) TF_RND(29) TF_RND(16) TF_RND(24)
    x0 += ks2; x1 += ks0 + 2u;
    TF_RND(13) TF_RND(15) TF_RND(26) TF_RND(6)
    x0 += ks0; x1 += ks1 + 3u;
    TF_RND(17) TF_RND(29) TF_RND(16) TF_RND(24)
    x0 += ks1; x1 += ks2 + 4u;
    TF_RND(13) TF_RND(15) TF_RND(26) TF_RND(6)
    x0 += ks2; x1 += ks0 + 5u;
#undef TF_RND
    y0 = x0; y1 = x1;
}

__device__ __forceinline__ float sigf(float z) { return 1.0f / (1.0f + expf(-z)); }

// JAX partitionable PRNG semantics (VERIFIED rel_err 2.7e-7 in fp32 run — do not touch):
//   split(key):  keys[i] = threefry(key, (0, i))  -> key=keys[0], sub=keys[1]
//   bits(sub,n): bits[i] = y0 ^ y1 of threefry(sub, (0, i))
// Local-state version: every block runs this identically (deterministic), keys stay in sync.
__device__ int d_sample_local(const float* L, int n,
                              uint32_t& key0, uint32_t& key1,
                              float& lp, float& ent) {
    uint32_t nk0, nk1, sk0, sk1;
    tf2x32(key0, key1, 0u, 0u, nk0, nk1);
    tf2x32(key0, key1, 0u, 1u, sk0, sk1);
    key0 = nk0; key1 = nk1;

    float best = 0.0f; int idx = 0;
    for (int i = 0; i < n; i++) {
        uint32_t b0, b1;
        tf2x32(sk0, sk1, 0u, (uint32_t)i, b0, b1);
        uint32_t bits = b0 ^ b1;
        float f = __uint_as_float((bits >> 9) | 0x3f800000u) - 1.0f;
        float u = (f > 0.0f) ? f : 1.17549435e-38f;
        float z = L[i] - logf(-logf(u));
        if (i == 0 || z > best) { best = z; idx = i; }
    }
    float m = L[0];
    for (int i = 1; i < n; i++) m = fmaxf(m, L[i]);
    float se = 0.0f;
    for (int i = 0; i < n; i++) se += expf(L[i] - m);
    float lse = m + logf(se);
    float e = 0.0f;
    for (int i = 0; i < n; i++) { float l = L[i] - lse; e -= l * expf(l); }
    lp  += -(L[idx] - lse);
    ent += e;
    return idx;
}

// ---------------- helpers ----------------
__device__ __forceinline__ float bdot8(uint4 w, float4 a, float4 b) {
    float2 f0 = __bfloat1622float2(*(__nv_bfloat162*)&w.x);
    float2 f1 = __bfloat1622float2(*(__nv_bfloat162*)&w.y);
    float2 f2 = __bfloat1622float2(*(__nv_bfloat162*)&w.z);
    float2 f3 = __bfloat1622float2(*(__nv_bfloat162*)&w.w);
    return f0.x * a.x + f0.y * a.y + f1.x * a.z + f1.y * a.w
         + f2.x * b.x + f2.y * b.y + f3.x * b.z + f3.y * b.w;
}

// warp-level dot of one bf16 row (H elems = 256 uint4) with h; lane0 holds result
__device__ __forceinline__ float warp_browdot(const uint4* __restrict__ wr,
                                              const float4* __restrict__ h4, int lane) {
    float s = 0.f;
#pragma unroll
    for (int i = 0; i < 8; i++) {
        int u = lane + 32 * i;
        s += bdot8(wr[u], h4[2 * u], h4[2 * u + 1]);
    }
    for (int o = 16; o > 0; o >>= 1) s += __shfl_down_sync(0xffffffffu, s, o);
    return s;
}

// ---------------- weight conversion (fp32 -> bf16) + bias fuse ----------------
__global__ __launch_bounds__(256) void k_convert(
    const float* __restrict__ w_ih, const float* __restrict__ w_hh,
    const float* __restrict__ w1, const float* __restrict__ w2,
    const float* __restrict__ b_ih, const float* __restrict__ b_hh) {
    const size_t n4 = (size_t)4 * H * H / 4;
    const size_t m4 = (size_t)H * H / 4;
    size_t i = (size_t)blockIdx.x * blockDim.x + threadIdx.x;
    if (i < n4) {
        float4 a = ((const float4*)w_ih)[i];
        float4 b = ((const float4*)w_hh)[i];
        __nv_bfloat162* oi = (__nv_bfloat162*)g_wih_bf;
        __nv_bfloat162* oh = (__nv_bfloat162*)g_whh_bf;
        oi[2 * i]     = __floats2bfloat162_rn(a.x, a.y);
        oi[2 * i + 1] = __floats2bfloat162_rn(a.z, a.w);
        oh[2 * i]     = __floats2bfloat162_rn(b.x, b.y);
        oh[2 * i + 1] = __floats2bfloat162_rn(b.z, b.w);
    }
    if (i < m4) {
        float4 a = ((const float4*)w1)[i];
        float4 b = ((const float4*)w2)[i];
        __nv_bfloat162* o1 = (__nv_bfloat162*)g_w1_bf;
        __nv_bfloat162* o2 = (__nv_bfloat162*)g_w2_bf;
        o1[2 * i]     = __floats2bfloat162_rn(a.x, a.y);
        o1[2 * i + 1] = __floats2bfloat162_rn(a.z, a.w);
        o2[2 * i]     = __floats2bfloat162_rn(b.x, b.y);
        o2[2 * i + 1] = __floats2bfloat162_rn(b.z, b.w);
    }
    if (i < 4 * H) g_bias[i] = b_ih[i] + b_hh[i];
}

// ---------------- precompute w_ih @ enc[k]^T for all 9 encoder rows (fp32) ----------------
__global__ __launch_bounds__(256) void k_precomp(const float* __restrict__ w_ih,
                                                 const float* __restrict__ enc) {
    const int g = blockIdx.x;   // output row 0..4H-1
    const int t = threadIdx.x;
    const float4* __restrict__ wr = (const float4*)(w_ih + (size_t)g * H);
    float4 a0 = wr[t], a1 = wr[t + 256];
    float acc[NENC];
#pragma unroll
    for (int k = 0; k < NENC; k++) {
        const float4* __restrict__ e4 = (const float4*)(enc + (size_t)k * H);
        float4 e0 = e4[t], e1 = e4[t + 256];
        acc[k] = a0.x * e0.x + a0.y * e0.y + a0.z * e0.z + a0.w * e0.w
               + a1.x * e1.x + a1.y * e1.y + a1.z * e1.z + a1.w * e1.w;
    }
    __shared__ float sb[8][NENC];
#pragma unroll
    for (int k = 0; k < NENC; k++) {
        float s = acc[k];
        for (int o = 16; o > 0; o >>= 1) s += __shfl_down_sync(0xffffffffu, s, o);
        if ((t & 31) == 0) sb[t >> 5][k] = s;
    }
    __syncthreads();
    if (t < NENC) {
        float r = 0.f;
        for (int w = 0; w < 8; w++) r += sb[w][t];
        g_wih_pre[t][g] = r;
    }
}

// ---------------- reset barrier state (stream-ordered before persistent kernel) ----------------
__global__ void k_reset() {
    g_bar_count = 0u;
    g_bar_gen = 0u;
}

// ---------------- THE persistent kernel ----------------
__global__ __launch_bounds__(NTHR, 1) void k_persist(
    const float* __restrict__ w_soft, const float* __restrict__ b_soft,
    const float* __restrict__ b_nl, const float* __restrict__ v,
    float* __restrict__ out, int out_size)
{
    const int tid  = threadIdx.x;
    const int blk  = blockIdx.x;
    const int lane = tid & 31;
    const int widx = tid >> 5;

    unsigned lgen = 0;              // thread0-only barrier generation
    uint32_t key0 = 0u, key1 = 42u; // thread0-only PRNG state (replicated per block)
    float lp = 0.f, ent = 0.f;

    __shared__ int   s_xrow;
    __shared__ float s_gates[16][4];
    __shared__ float s_log[16];
    __shared__ float s_arc[64];     // only block0's copy matters

    // ---- init h, c ----
    {
        int idx = blk * NTHR + tid;
        if (idx < H) { g_h[0][idx] = 0.f; g_h[1][idx] = 0.f; g_c[idx] = 0.f; }
    }
    int par = 0;
    grid_bar(lgen);

    for (int s = 0; s < 2; s++) {
        const int use_bias = (s == 0);
        // zero anchor-precompute slots 9,10 (warmup anchors are zero vectors)
        {
            int idx = blk * NTHR + tid;
            if (idx < 4 * H) {
                g_wih_pre[NENC + 0][idx] = 0.f;
                g_wih_pre[NENC + 1][idx] = 0.f;
            }
        }
        if (tid == 0) s_xrow = 0;
        grid_bar(lgen);

        // ================= stages =================
        // macro-ish lambdas via code blocks
        for (int a = 0; a < 2; a++) {
            // --- cell ---
            {
                const int xrow = s_xrow;
                const int slot = widx >> 1, half = widx & 1;
                const int j = blk * 16 + slot;
                const float4* h4 = (const float4*)g_h[par];
                if (j < H) {
                    const uint4* wA = (const uint4*)(g_whh_bf + (size_t)((2 * half) * H + j) * H);
                    const uint4* wB = (const uint4*)(g_whh_bf + (size_t)((2 * half + 1) * H + j) * H);
                    float sA = warp_browdot(wA, h4, lane);
                    float sB = warp_browdot(wB, h4, lane);
                    if (lane == 0) { s_gates[slot][2 * half] = sA; s_gates[slot][2 * half + 1] = sB; }
                }
                __syncthreads();
                if (tid < 16) {
                    int jj = blk * 16 + tid;
                    if (jj < H) {
                        float r0 = s_gates[tid][0] + g_wih_pre[xrow][0 * H + jj] + g_bias[0 * H + jj];
                        float r1 = s_gates[tid][1] + g_wih_pre[xrow][1 * H + jj] + g_bias[1 * H + jj];
                        float r2 = s_gates[tid][2] + g_wih_pre[xrow][2 * H + jj] + g_bias[2 * H + jj];
                        float r3 = s_gates[tid][3] + g_wih_pre[xrow][3 * H + jj] + g_bias[3 * H + jj];
                        float gi = sigf(r0), gf = sigf(r1), gg = tanhf(r2), go = sigf(r3);
                        float c2 = gf * g_c[jj] + gi * gg;
                        g_c[jj] = c2;
                        g_h[par ^ 1][jj] = go * tanhf(c2);
                    }
                }
            }
            par ^= 1;
            grid_bar(lgen);
            // --- aw1[a] = h @ W1^T ---
            {
                const float4* h4 = (const float4*)g_h[par];
                int gw = blk * 32 + widx;
                if (gw < H) {
                    float s2 = warp_browdot((const uint4*)(g_w1_bf + (size_t)gw * H), h4, lane);
                    if (lane == 0) g_aw1[a][gw] = s2;
                }
            }
            grid_bar(lgen);
        }

        for (int layer = 2; layer < 10; layer++) {
            const int base = s * 32 + 4 * (layer - 2);
            // ---- 2 attention samples ----
            for (int t2 = 0; t2 < 2; t2++) {
                // --- cell ---
                {
                    const int xrow = s_xrow;
                    const int slot = widx >> 1, half = widx & 1;
                    const int j = blk * 16 + slot;
                    const float4* h4 = (const float4*)g_h[par];
                    if (j < H) {
                        const uint4* wA = (const uint4*)(g_whh_bf + (size_t)((2 * half) * H + j) * H);
                        const uint4* wB = (const uint4*)(g_whh_bf + (size_t)((2 * half + 1) * H + j) * H);
                        float sA = warp_browdot(wA, h4, lane);
                        float sB = warp_browdot(wB, h4, lane);
                        if (lane == 0) { s_gates[slot][2 * half] = sA; s_gates[slot][2 * half + 1] = sB; }
                    }
                    __syncthreads();
                    if (tid < 16) {
                        int jj = blk * 16 + tid;
                        if (jj < H) {
                            float r0 = s_gates[tid][0] + g_wih_pre[xrow][0 * H + jj] + g_bias[0 * H + jj];
                            float r1 = s_gates[tid][1] + g_wih_pre[xrow][1 * H + jj] + g_bias[1 * H + jj];
                            float r2 = s_gates[tid][2] + g_wih_pre[xrow][2 * H + jj] + g_bias[2 * H + jj];
                            float r3 = s_gates[tid][3] + g_wih_pre[xrow][3 * H + jj] + g_bias[3 * H + jj];
                            float gi = sigf(r0), gf = sigf(r1), gg = tanhf(r2), go = sigf(r3);
                            float c2 = gf * g_c[jj] + gi * gg;
                            g_c[jj] = c2;
                            g_h[par ^ 1][jj] = go * tanhf(c2);
                        }
                    }
                }
                par ^= 1;
                grid_bar(lgen);
                // --- g_r = h @ W2^T ---
                {
                    const float4* h4 = (const float4*)g_h[par];
                    int gw = blk * 32 + widx;
                    if (gw < H) {
                        float s2 = warp_browdot((const uint4*)(g_w2_bf + (size_t)gw * H), h4, lane);
                        if (lane == 0) g_r[gw] = s2;
                    }
                }
                grid_bar(lgen);
                // --- attention tail (redundant per block, no barrier) ---
                {
                    const int n = layer;
                    if (widx < n) {
                        float s2 = 0.f;
                        const float* aw = g_aw1[widx];
                        for (int k = lane; k < H; k += 32)
                            s2 += v[k] * tanhf(aw[k] + g_r[k]);
                        for (int o = 16; o > 0; o >>= 1) s2 += __shfl_down_sync(0xffffffffu, s2, o);
                        if (lane == 0) s_log[widx] = s2;
                    }
                    __syncthreads();
                    if (tid == 0) {
                        float L[MAXA];
                        for (int l = 0; l < n; l++) L[l] = 2.5f * tanhf(s_log[l] * 0.2f);
                        int idx = d_sample_local(L, n, key0, key1, lp, ent);
                        s_xrow = NENC + idx;
                        if (blk == 0) s_arc[base + (t2 ? 2 : 0)] = (float)idx;
                    }
                    __syncthreads();
                }
            }
            // ---- 2 op samples ----
            for (int t2 = 0; t2 < 2; t2++) {
                // --- cell ---
                {
                    const int xrow = s_xrow;
                    const int slot = widx >> 1, half = widx & 1;
                    const int j = blk * 16 + slot;
                    const float4* h4 = (const float4*)g_h[par];
                    if (j < H) {
                        const uint4* wA = (const uint4*)(g_whh_bf + (size_t)((2 * half) * H + j) * H);
                        const uint4* wB = (const uint4*)(g_whh_bf + (size_t)((2 * half + 1) * H + j) * H);
                        float sA = warp_browdot(wA, h4, lane);
                        float sB = warp_browdot(wB, h4, lane);
                        if (lane == 0) { s_gates[slot][2 * half] = sA; s_gates[slot][2 * half + 1] = sB; }
                    }
                    __syncthreads();
                    if (tid < 16) {
                        int jj = blk * 16 + tid;
                        if (jj < H) {
                            float r0 = s_gates[tid][0] + g_wih_pre[xrow][0 * H + jj] + g_bias[0 * H + jj];
                            float r1 = s_gates[tid][1] + g_wih_pre[xrow][1 * H + jj] + g_bias[1 * H + jj];
                            float r2 = s_gates[tid][2] + g_wih_pre[xrow][2 * H + jj] + g_bias[2 * H + jj];
                            float r3 = s_gates[tid][3] + g_wih_pre[xrow][3 * H + jj] + g_bias[3 * H + jj];
                            float gi = sigf(r0), gf = sigf(r1), gg = tanhf(r2), go = sigf(r3);
                            float c2 = gf * g_c[jj] + gi * gg;
                            g_c[jj] = c2;
                            g_h[par ^ 1][jj] = go * tanhf(c2);
                        }
                    }
                }
                par ^= 1;
                grid_bar(lgen);
                // --- op tail (redundant per block) ---
                {
                    const float4* h4 = (const float4*)g_h[par];
                    if (widx < NBOP) {
                        const float4* wr = (const float4*)(w_soft + (size_t)widx * H);
                        float s2 = 0.f;
                        for (int i = lane; i < H / 4; i += 32) {
                            float4 a = wr[i], b = h4[i];
                            s2 += a.x * b.x + a.y * b.y + a.z * b.z + a.w * b.w;
                        }
                        for (int o = 16; o > 0; o >>= 1) s2 += __shfl_down_sync(0xffffffffu, s2, o);
                        if (lane == 0) s_log[widx] = s2;
                    }
                    __syncthreads();
                    if (tid == 0) {
                        float L[NBOP];
                        for (int o = 0; o < NBOP; o++) {
                            L[o] = tanhf((s_log[o] + b_soft[o]) * 0.2f);
                            if (use_bias) L[o] += b_nl[o];
                        }
                        int op = d_sample_local(L, NBOP, key0, key1, lp, ent);
                        s_xrow = op + 1;
                        if (blk == 0) s_arc[base + 1 + 2 * t2] = (float)op;
                    }
                    __syncthreads();
                }
            }
            // ---- anchor cell ----
            {
                const int xrow = s_xrow;
                const int slot = widx >> 1, half = widx & 1;
                const int j = blk * 16 + slot;
                const float4* h4 = (const float4*)g_h[par];
                if (j < H) {
                    const uint4* wA = (const uint4*)(g_whh_bf + (size_t)((2 * half) * H + j) * H);
                    const uint4* wB = (const uint4*)(g_whh_bf + (size_t)((2 * half + 1) * H + j) * H);
                    float sA = warp_browdot(wA, h4, lane);
                    float sB = warp_browdot(wB, h4, lane);
                    if (lane == 0) { s_gates[slot][2 * half] = sA; s_gates[slot][2 * half + 1] = sB; }
                }
                __syncthreads();
                if (tid < 16) {
                    int jj = blk * 16 + tid;
                    if (jj < H) {
                        float r0 = s_gates[tid][0] + g_wih_pre[xrow][0 * H + jj] + g_bias[0 * H + jj];
                        float r1 = s_gates[tid][1] + g_wih_pre[xrow][1 * H + jj] + g_bias[1 * H + jj];
                        float r2 = s_gates[tid][2] + g_wih_pre[xrow][2 * H + jj] + g_bias[2 * H + jj];
                        float r3 = s_gates[tid][3] + g_wih_pre[xrow][3 * H + jj] + g_bias[3 * H + jj];
                        float gi = sigf(r0), gf = sigf(r1), gg = tanhf(r2), go = sigf(r3);
                        float c2 = gf * g_c[jj] + gi * gg;
                        g_c[jj] = c2;
                        g_h[par ^ 1][jj] = go * tanhf(c2);
                    }
                }
            }
            par ^= 1;
            grid_bar(lgen);
            // ---- record: aw1[layer] = h@W1^T  AND  wih_pre[NENC+layer] = w_ih@h ----
            {
                const float4* h4 = (const float4*)g_h[par];
                for (int gw = blk * 32 + widx; gw < 5 * H; gw += NBLK * 32) {
                    const uint4* wr = (gw < H)
                        ? (const uint4*)(g_w1_bf + (size_t)gw * H)
                        : (const uint4*)(g_wih_bf + (size_t)(gw - H) * H);
                    float s2 = warp_browdot(wr, h4, lane);
                    if (lane == 0) {
                        if (gw < H) g_aw1[layer][gw] = s2;
                        else        g_wih_pre[NENC + layer][gw - H] = s2;
                    }
                }
                if (tid == 0) s_xrow = 0;   // inputs reset to encoder_w[0]
            }
            grid_bar(lgen);
        }
    }

    // ---- output (block 0) ----
    if (blk == 0) {
        __syncthreads();
        for (int i = tid; i < out_size; i += NTHR) {
            float val = 0.f;
            if (i < 64) val = s_arc[i];
            out[i] = val;
        }
        if (tid == 0) {
            if (out_size > 64) out[64] = lp;
            if (out_size > 65) out[65] = ent;
        }
    }
}

// ---------------- host schedule ----------------
extern "C" void kernel_launch(void* const* d_in, const int* in_sizes, int n_in,
                              void* d_out, int out_size) {
    const float* enc    = (const float*)d_in[0];
    const float* w_ih   = (const float*)d_in[1];
    const float* b_ih   = (const float*)d_in[2];
    const float* w_hh   = (const float*)d_in[3];
    const float* b_hh   = (const float*)d_in[4];
    const float* w_soft = (const float*)d_in[5];
    const float* b_soft = (const float*)d_in[6];
    const float* b_nl   = (const float*)d_in[7];
    const float* w1     = (const float*)d_in[8];
    const float* w2     = (const float*)d_in[9];
    const float* v      = (const float*)d_in[10];

    {
        size_t n4 = (size_t)4 * H * H / 4;
        int blocks = (int)((n4 + 255) / 256);
        k_convert<<<blocks, 256>>>(w_ih, w_hh, w1, w2, b_ih, b_hh);
    }
    k_precomp<<<4 * H, 256>>>(w_ih, enc);
    k_reset<<<1, 1>>>();
    k_persist<<<NBLK, NTHR>>>(w_soft, b_soft, b_nl, v, (float*)d_out, out_size);
}

// round 17
// speedup vs baseline: 1.4221x; 1.3108x over previous
#include <cuda_runtime.h>
#include <cuda_bf16.h>
#include <cstdint>
#include <math.h>

#define H 2048
#define NBOP 8
#define MAXA 10
#define NENC 9             // NB + 1 encoder rows
#define NPRE (NENC + MAXA) // 19 precomputed w_ih@x rows: 0..8 enc, 9..18 anchors
#define NBLK 148
#define NTHR 1024

// ---------------- device state ----------------
__device__ __align__(16) float g_h[2][H];
__device__ __align__(16) float g_c[H];
__device__ __align__(16) float g_aw1[MAXA][H];
__device__ __align__(16) float g_r[H];
__device__ __align__(16) float g_bias[4 * H];                 // b_ih + b_hh
__device__ __align__(16) float g_wih_pre[NPRE][4 * H];        // w_ih @ x for all possible x
__device__ __align__(16) __nv_bfloat16 g_wih_bf[4 * H * H];   // 33.5 MB
__device__ __align__(16) __nv_bfloat16 g_whh_bf[4 * H * H];   // 33.5 MB
__device__ __align__(16) __nv_bfloat16 g_w1_bf[H * H];        // 8.4 MB
__device__ __align__(16) __nv_bfloat16 g_w2_bf[H * H];        // 8.4 MB
__device__ unsigned g_bar_count;
__device__ volatile unsigned g_bar_gen;

struct Sh {
    int   xrow;
    float gates[16][4];
    float logit[16];
    float arc[64];
};

// ---------------- grid barrier (state reset by k_reset before each replay) ----------------
__device__ __forceinline__ void grid_bar(unsigned& lgen) {
    __syncthreads();
    if (threadIdx.x == 0) {
        unsigned target = ++lgen;
        __threadfence();
        if (atomicAdd(&g_bar_count, 1u) == (unsigned)(NBLK - 1)) {
            g_bar_count = 0u;
            __threadfence();
            g_bar_gen = target;
        } else {
            while (g_bar_gen < target) {}
        }
    }
    __syncthreads();
}

// ---------------- threefry2x32 (20 rounds) ----------------
__device__ __forceinline__ uint32_t rotl32(uint32_t v, int d) {
    return (v << d) | (v >> (32 - d));
}

__device__ __forceinline__ void tf2x32(uint32_t k0, uint32_t k1,
                                       uint32_t x0, uint32_t x1,
                                       uint32_t& y0, uint32_t& y1) {
    uint32_t ks0 = k0, ks1 = k1, ks2 = 0x1BD11BDAu ^ k0 ^ k1;
    x0 += ks0; x1 += ks1;
#define TF_RND(r) { x0 += x1; x1 = rotl32(x1, r); x1 ^= x0; }
    TF_RND(13) TF_RND(15) TF_RND(26) TF_RND(6)
    x0 += ks1; x1 += ks2 + 1u;
    TF_RND(17) TF_RND(29) TF_RND(16) TF_RND(24)
    x0 += ks2; x1 += ks0 + 2u;
    TF_RND(13) TF_RND(15) TF_RND(26) TF_RND(6)
    x0 += ks0; x1 += ks1 + 3u;
    TF_RND(17) TF_RND(29) TF_RND(16) TF_RND(24)
    x0 += ks1; x1 += ks2 + 4u;
    TF_RND(13) TF_RND(15) TF_RND(26) TF_RND(6)
    x0 += ks2; x1 += ks0 + 5u;
#undef TF_RND
    y0 = x0; y1 = x1;
}

__device__ __forceinline__ float sigf(float z) { return 1.0f / (1.0f + expf(-z)); }

// JAX partitionable PRNG semantics (VERIFIED rel_err 2.7e-7 in fp32 run — do not touch):
//   split(key):  keys[i] = threefry(key, (0, i))  -> key=keys[0], sub=keys[1]
//   bits(sub,n): bits[i] = y0 ^ y1 of threefry(sub, (0, i))
// Runs redundantly & deterministically per block; per-block keys stay in sync.
__device__ int d_sample_local(const float* L, int n,
                              uint32_t& key0, uint32_t& key1,
                              float& lp, float& ent) {
    uint32_t nk0, nk1, sk0, sk1;
    tf2x32(key0, key1, 0u, 0u, nk0, nk1);
    tf2x32(key0, key1, 0u, 1u, sk0, sk1);
    key0 = nk0; key1 = nk1;

    float best = 0.0f; int idx = 0;
    for (int i = 0; i < n; i++) {
        uint32_t b0, b1;
        tf2x32(sk0, sk1, 0u, (uint32_t)i, b0, b1);
        uint32_t bits = b0 ^ b1;
        float f = __uint_as_float((bits >> 9) | 0x3f800000u) - 1.0f;
        float u = (f > 0.0f) ? f : 1.17549435e-38f;
        float z = L[i] - logf(-logf(u));
        if (i == 0 || z > best) { best = z; idx = i; }
    }
    float m = L[0];
    for (int i = 1; i < n; i++) m = fmaxf(m, L[i]);
    float se = 0.0f;
    for (int i = 0; i < n; i++) se += expf(L[i] - m);
    float lse = m + logf(se);
    float e = 0.0f;
    for (int i = 0; i < n; i++) { float l = L[i] - lse; e -= l * expf(l); }
    lp  += -(L[idx] - lse);
    ent += e;
    return idx;
}

// ---------------- helpers ----------------
__device__ __forceinline__ float bdot8(uint4 w, float4 a, float4 b) {
    float2 f0 = __bfloat1622float2(*(__nv_bfloat162*)&w.x);
    float2 f1 = __bfloat1622float2(*(__nv_bfloat162*)&w.y);
    float2 f2 = __bfloat1622float2(*(__nv_bfloat162*)&w.z);
    float2 f3 = __bfloat1622float2(*(__nv_bfloat162*)&w.w);
    return f0.x * a.x + f0.y * a.y + f1.x * a.z + f1.y * a.w
         + f2.x * b.x + f2.y * b.y + f3.x * b.z + f3.y * b.w;
}

// warp dot of one bf16 row (H elems = 256 uint4) with h; lane0 holds result
__device__ __forceinline__ float warp_browdot(const uint4* __restrict__ wr,
                                              const float4* __restrict__ h4, int lane) {
    float s = 0.f;
#pragma unroll
    for (int i = 0; i < 8; i++) {
        int u = lane + 32 * i;
        s += bdot8(wr[u], h4[2 * u], h4[2 * u + 1]);
    }
    for (int o = 16; o > 0; o >>= 1) s += __shfl_down_sync(0xffffffffu, s, o);
    return s;
}

// ---------------- stage bodies (all read g_h[par]; cell writes g_h[par^1]) ----------------
// LSTM cell: 16 outputs/block, 2 warps per output (2 gate rows each), interleaved loads.
__device__ __forceinline__ void do_cell(Sh* sh, int blk, int tid, int lane, int widx,
                                        int par, int xrow_static) {
    const int slot = widx >> 1, half = widx & 1;
    const int j = blk * 16 + slot;
    const float4* __restrict__ h4 = (const float4*)g_h[par];
    if (j < H) {
        const uint4* __restrict__ wA = (const uint4*)(g_whh_bf + (size_t)((2 * half) * H + j) * H);
        const uint4* __restrict__ wB = (const uint4*)(g_whh_bf + (size_t)((2 * half + 1) * H + j) * H);
        float sA = 0.f, sB = 0.f;
#pragma unroll
        for (int i = 0; i < 8; i++) {
            int u = lane + 32 * i;
            uint4 a = wA[u];
            uint4 b = wB[u];
            float4 h0 = h4[2 * u], h1 = h4[2 * u + 1];
            sA += bdot8(a, h0, h1);
            sB += bdot8(b, h0, h1);
        }
        for (int o = 16; o > 0; o >>= 1) {
            sA += __shfl_down_sync(0xffffffffu, sA, o);
            sB += __shfl_down_sync(0xffffffffu, sB, o);
        }
        if (lane == 0) { sh->gates[slot][2 * half] = sA; sh->gates[slot][2 * half + 1] = sB; }
    }
    __syncthreads();
    if (tid < 16) {
        int jj = blk * 16 + tid;
        if (jj < H) {
            const int xrow = (xrow_static >= 0) ? xrow_static : sh->xrow;
            float r0 = sh->gates[tid][0] + g_wih_pre[xrow][0 * H + jj] + g_bias[0 * H + jj];
            float r1 = sh->gates[tid][1] + g_wih_pre[xrow][1 * H + jj] + g_bias[1 * H + jj];
            float r2 = sh->gates[tid][2] + g_wih_pre[xrow][2 * H + jj] + g_bias[2 * H + jj];
            float r3 = sh->gates[tid][3] + g_wih_pre[xrow][3 * H + jj] + g_bias[3 * H + jj];
            float gi = sigf(r0), gf = sigf(r1), gg = tanhf(r2), go = sigf(r3);
            float c2 = gf * g_c[jj] + gi * gg;
            g_c[jj] = c2;
            g_h[par ^ 1][jj] = go * tanhf(c2);
        }
    }
}

// aw1[a] = h @ W1^T (warm-up record, anchors are zero vectors)
__device__ __forceinline__ void do_w1(int a, int blk, int widx, int lane, int par) {
    const float4* __restrict__ h4 = (const float4*)g_h[par];
    int gw = blk * 32 + widx;
    if (gw < H) {
        float s = warp_browdot((const uint4*)(g_w1_bf + (size_t)gw * H), h4, lane);
        if (lane == 0) g_aw1[a][gw] = s;
    }
}

// g_r = h @ W2^T
__device__ __forceinline__ void do_gemv(int blk, int widx, int lane, int par) {
    const float4* __restrict__ h4 = (const float4*)g_h[par];
    int gw = blk * 32 + widx;
    if (gw < H) {
        float s = warp_browdot((const uint4*)(g_w2_bf + (size_t)gw * H), h4, lane);
        if (lane == 0) g_r[gw] = s;
    }
}

// full anchor record: aw1[layer] = h@W1^T AND wih_pre[NENC+layer] = w_ih@h (5H rows)
__device__ __forceinline__ void do_record(int blk, int widx, int lane, int par, int layer) {
    const float4* __restrict__ h4 = (const float4*)g_h[par];
    for (int gw = blk * 32 + widx; gw < 5 * H; gw += NBLK * 32) {
        const uint4* __restrict__ wr = (gw < H)
            ? (const uint4*)(g_w1_bf + (size_t)gw * H)
            : (const uint4*)(g_wih_bf + (size_t)(gw - H) * H);
        float s = warp_browdot(wr, h4, lane);
        if (lane == 0) {
            if (gw < H) g_aw1[layer][gw] = s;
            else        g_wih_pre[NENC + layer][gw - H] = s;
        }
    }
}

// attention logits + sample (redundant per block); sets sh->xrow
__device__ __forceinline__ void att_tail(Sh* sh, int tid, int lane, int widx, int n,
                                         const float* __restrict__ v, int slot, int blk,
                                         uint32_t& key0, uint32_t& key1,
                                         float& lp, float& ent) {
    if (widx < n) {
        float s = 0.f;
        const float* __restrict__ aw = g_aw1[widx];
        for (int k = lane; k < H; k += 32)
            s += v[k] * tanhf(aw[k] + g_r[k]);
        for (int o = 16; o > 0; o >>= 1) s += __shfl_down_sync(0xffffffffu, s, o);
        if (lane == 0) sh->logit[widx] = s;
    }
    __syncthreads();
    if (tid == 0) {
        float L[MAXA];
        for (int l = 0; l < n; l++) L[l] = 2.5f * tanhf(sh->logit[l] * 0.2f);
        int idx = d_sample_local(L, n, key0, key1, lp, ent);
        sh->xrow = NENC + idx;
        if (blk == 0) sh->arc[slot] = (float)idx;
    }
    // ordering to readers of sh->xrow via the following do_cell's internal __syncthreads
}

// op logits + sample (redundant per block); sets sh->xrow
__device__ __forceinline__ void op_tail(Sh* sh, int tid, int lane, int widx, int par,
                                        const float* __restrict__ w_soft,
                                        const float* __restrict__ b_soft,
                                        const float* __restrict__ b_nl,
                                        int use_bias, int slot, int blk,
                                        uint32_t& key0, uint32_t& key1,
                                        float& lp, float& ent) {
    const float4* __restrict__ h4 = (const float4*)g_h[par];
    if (widx < NBOP) {
        const float4* __restrict__ wr = (const float4*)(w_soft + (size_t)widx * H);
        float s = 0.f;
        for (int i = lane; i < H / 4; i += 32) {
            float4 a = wr[i], b = h4[i];
            s += a.x * b.x + a.y * b.y + a.z * b.z + a.w * b.w;
        }
        for (int o = 16; o > 0; o >>= 1) s += __shfl_down_sync(0xffffffffu, s, o);
        if (lane == 0) sh->logit[widx] = s;
    }
    __syncthreads();
    if (tid == 0) {
        float L[NBOP];
        for (int o = 0; o < NBOP; o++) {
            L[o] = tanhf((sh->logit[o] + b_soft[o]) * 0.2f);
            if (use_bias) L[o] += b_nl[o];
        }
        int op = d_sample_local(L, NBOP, key0, key1, lp, ent);
        sh->xrow = op + 1;
        if (blk == 0) sh->arc[slot] = (float)op;
    }
}

// ---------------- weight conversion (fp32 -> bf16) + bias fuse ----------------
__global__ __launch_bounds__(256) void k_convert(
    const float* __restrict__ w_ih, const float* __restrict__ w_hh,
    const float* __restrict__ w1, const float* __restrict__ w2,
    const float* __restrict__ b_ih, const float* __restrict__ b_hh) {
    const size_t n4 = (size_t)4 * H * H / 4;
    const size_t m4 = (size_t)H * H / 4;
    size_t i = (size_t)blockIdx.x * blockDim.x + threadIdx.x;
    if (i < n4) {
        float4 a = ((const float4*)w_ih)[i];
        float4 b = ((const float4*)w_hh)[i];
        __nv_bfloat162* oi = (__nv_bfloat162*)g_wih_bf;
        __nv_bfloat162* oh = (__nv_bfloat162*)g_whh_bf;
        oi[2 * i]     = __floats2bfloat162_rn(a.x, a.y);
        oi[2 * i + 1] = __floats2bfloat162_rn(a.z, a.w);
        oh[2 * i]     = __floats2bfloat162_rn(b.x, b.y);
        oh[2 * i + 1] = __floats2bfloat162_rn(b.z, b.w);
    }
    if (i < m4) {
        float4 a = ((const float4*)w1)[i];
        float4 b = ((const float4*)w2)[i];
        __nv_bfloat162* o1 = (__nv_bfloat162*)g_w1_bf;
        __nv_bfloat162* o2 = (__nv_bfloat162*)g_w2_bf;
        o1[2 * i]     = __floats2bfloat162_rn(a.x, a.y);
        o1[2 * i + 1] = __floats2bfloat162_rn(a.z, a.w);
        o2[2 * i]     = __floats2bfloat162_rn(b.x, b.y);
        o2[2 * i + 1] = __floats2bfloat162_rn(b.z, b.w);
    }
    if (i < 4 * H) g_bias[i] = b_ih[i] + b_hh[i];
}

// ---------------- precompute w_ih @ enc[k]^T for all 9 encoder rows (fp32) ----------------
__global__ __launch_bounds__(256) void k_precomp(const float* __restrict__ w_ih,
                                                 const float* __restrict__ enc) {
    const int g = blockIdx.x;   // output row 0..4H-1
    const int t = threadIdx.x;
    const float4* __restrict__ wr = (const float4*)(w_ih + (size_t)g * H);
    float4 a0 = wr[t], a1 = wr[t + 256];
    float acc[NENC];
#pragma unroll
    for (int k = 0; k < NENC; k++) {
        const float4* __restrict__ e4 = (const float4*)(enc + (size_t)k * H);
        float4 e0 = e4[t], e1 = e4[t + 256];
        acc[k] = a0.x * e0.x + a0.y * e0.y + a0.z * e0.z + a0.w * e0.w
               + a1.x * e1.x + a1.y * e1.y + a1.z * e1.z + a1.w * e1.w;
    }
    __shared__ float sb[8][NENC];
#pragma unroll
    for (int k = 0; k < NENC; k++) {
        float s = acc[k];
        for (int o = 16; o > 0; o >>= 1) s += __shfl_down_sync(0xffffffffu, s, o);
        if ((t & 31) == 0) sb[t >> 5][k] = s;
    }
    __syncthreads();
    if (t < NENC) {
        float r = 0.f;
        for (int w = 0; w < 8; w++) r += sb[w][t];
        g_wih_pre[t][g] = r;
    }
}

// ---------------- reset barrier state (stream-ordered before persistent kernel) ----------------
__global__ void k_reset() {
    g_bar_count = 0u;
    g_bar_gen = 0u;
}

// ---------------- THE persistent kernel ----------------
__global__ __launch_bounds__(NTHR, 1) void k_persist(
    const float* __restrict__ w_soft, const float* __restrict__ b_soft,
    const float* __restrict__ b_nl, const float* __restrict__ v,
    float* __restrict__ out, int out_size)
{
    const int tid  = threadIdx.x;
    const int blk  = blockIdx.x;
    const int lane = tid & 31;
    const int widx = tid >> 5;

    unsigned lgen = 0;
    uint32_t key0 = 0u, key1 = 42u;   // replicated PRNG state (thread0 of each block)
    float lp = 0.f, ent = 0.f;

    __shared__ Sh sh;

    // ---- Sz: zero h, c, and warm-up anchor precompute slots for sampler 0 ----
    {
        int idx = blk * NTHR + tid;
        if (idx < H) { g_h[0][idx] = 0.f; g_h[1][idx] = 0.f; g_c[idx] = 0.f; }
        if (idx < 4 * H) {
            g_wih_pre[NENC + 0][idx] = 0.f;
            g_wih_pre[NENC + 1][idx] = 0.f;
        }
    }
    int par = 0;
    grid_bar(lgen);

    for (int s = 0; s < 2; s++) {
        const int use_bias = (s == 0);

        // ---- A: cell0 (x=enc[0]); for s==1 also zero warm-up anchor slots ----
        if (s == 1) {
            int idx = blk * NTHR + tid;
            if (idx < 4 * H) {
                g_wih_pre[NENC + 0][idx] = 0.f;
                g_wih_pre[NENC + 1][idx] = 0.f;
            }
        }
        do_cell(&sh, blk, tid, lane, widx, par, 0); par ^= 1; grid_bar(lgen);

        // ---- B: aw1[0] + cell1 ----
        do_w1(0, blk, widx, lane, par);
        do_cell(&sh, blk, tid, lane, widx, par, 0); par ^= 1; grid_bar(lgen);

        // ---- C: aw1[1] + first idx cell of layer 2 (x = enc[0]) ----
        do_w1(1, blk, widx, lane, par);
        do_cell(&sh, blk, tid, lane, widx, par, 0); par ^= 1; grid_bar(lgen);

        for (int layer = 2; layer < 10; layer++) {
            const int base = s * 32 + 4 * (layer - 2);

            // ---- D: r = h @ W2^T ----
            do_gemv(blk, widx, lane, par); grid_bar(lgen);

            // ---- E: attention sample idx0 + idx cell 2 ----
            att_tail(&sh, tid, lane, widx, layer, v, base + 0, blk, key0, key1, lp, ent);
            do_cell(&sh, blk, tid, lane, widx, par, -1); par ^= 1; grid_bar(lgen);

            // ---- F: r = h @ W2^T ----
            do_gemv(blk, widx, lane, par); grid_bar(lgen);

            // ---- G: attention sample idx1 + op cell 1 ----
            att_tail(&sh, tid, lane, widx, layer, v, base + 2, blk, key0, key1, lp, ent);
            do_cell(&sh, blk, tid, lane, widx, par, -1); par ^= 1; grid_bar(lgen);

            // ---- H: op sample op0 + op cell 2 ----
            op_tail(&sh, tid, lane, widx, par, w_soft, b_soft, b_nl, use_bias,
                    base + 1, blk, key0, key1, lp, ent);
            do_cell(&sh, blk, tid, lane, widx, par, -1); par ^= 1; grid_bar(lgen);

            // ---- I: op sample op1 + anchor cell ----
            // (sampler 2, layer 9: the anchor cell's h,c are dead -> skip it)
            op_tail(&sh, tid, lane, widx, par, w_soft, b_soft, b_nl, use_bias,
                    base + 3, blk, key0, key1, lp, ent);
            if (!(s == 1 && layer == 9)) {
                do_cell(&sh, blk, tid, lane, widx, par, -1); par ^= 1; grid_bar(lgen);
                if (layer < 9) {
                    // ---- J: anchor record (aw1[layer] + wih_pre[NENC+layer])
                    //         fused with next layer's first idx cell (x = enc[0]) ----
                    do_record(blk, widx, lane, par, layer);
                    do_cell(&sh, blk, tid, lane, widx, par, 0); par ^= 1; grid_bar(lgen);
                }
                // layer == 9: anchor 9 is never attended -> no record needed.
            }
        }
    }

    // ---- output (block 0 only; s==1/layer==9 op_tail has no trailing cell) ----
    if (blk == 0) {
        __syncthreads();   // order thread0's last sample (arc[63], lp, ent)
        for (int i = tid; i < out_size; i += NTHR) {
            float val = 0.f;
            if (i < 64) val = sh.arc[i];
            out[i] = val;
        }
        if (tid == 0) {
            if (out_size > 64) out[64] = lp;
            if (out_size > 65) out[65] = ent;
        }
    }
}

// ---------------- host schedule ----------------
extern "C" void kernel_launch(void* const* d_in, const int* in_sizes, int n_in,
                              void* d_out, int out_size) {
    const float* enc    = (const float*)d_in[0];
    const float* w_ih   = (const float*)d_in[1];
    const float* b_ih   = (const float*)d_in[2];
    const float* w_hh   = (const float*)d_in[3];
    const float* b_hh   = (const float*)d_in[4];
    const float* w_soft = (const float*)d_in[5];
    const float* b_soft = (const float*)d_in[6];
    const float* b_nl   = (const float*)d_in[7];
    const float* w1     = (const float*)d_in[8];
    const float* w2     = (const float*)d_in[9];
    const float* v      = (const float*)d_in[10];

    {
        size_t n4 = (size_t)4 * H * H / 4;
        int blocks = (int)((n4 + 255) / 256);
        k_convert<<<blocks, 256>>>(w_ih, w_hh, w1, w2, b_ih, b_hh);
    }
    k_precomp<<<4 * H, 256>>>(w_ih, enc);
    k_reset<<<1, 1>>>();
    k_persist<<<NBLK, NTHR>>>(w_soft, b_soft, b_nl, v, (float*)d_out, out_size);
}